// round 14
// baseline (speedup 1.0000x reference)
#include <cuda_runtime.h>
#include <cuda_bf16.h>
#include <stdint.h>

#define N_NODES 100000
#define N_EDGES 1600000
#define IN_DIM  128
#define HID_DIM 64
#define OUT_DIM 64

#define GEMM_BLOCKS ((N_NODES + 255) / 256)       // 391
#define EDGE4_BLOCKS ((N_EDGES / 4 + 255) / 256)  // 1563
#define G1A 139                                   // gemm1 slice A (with hist)
#define G1B (GEMM_BLOCKS - G1A)                   // gemm1 slice B (with fill): 252
#define SCALE_BLOCKS ((N_NODES * 64) / 1024)      // 6250

// ---------------- scratch (static device globals; no allocation) -------------
// Zero-initialized at load; offsets re-zeroes g_cnt and hist resets g_total,
// so every graph replay sees identical state.
__device__ __align__(16) float g_h[N_NODES * 64];   // GEMM output
__device__ __align__(16) float g_a[N_NODES * 64];   // layer1 activations
__device__ __align__(16) int   g_cnt[N_NODES];      // hist counters
__device__ __align__(16) int   g_len[N_NODES];      // in-degree snapshot for agg
__device__ __align__(16) int   g_cur[N_NODES];      // fill cursor
__device__ __align__(16) float g_dinv[N_NODES];     // rsqrt(deg+1)
__device__ __align__(16) int   g_off[N_NODES];      // bucket start
__device__ __align__(16) int   g_src[N_EDGES];      // source id only
__device__ int g_total;                             // global bucket cursor

// ---------------- hist device body -------------------------------------------
__device__ __forceinline__ void hist_body(const int* __restrict__ eidx, int blk) {
    if (blk == 0 && threadIdx.x == 0) g_total = 0;
    int e0 = (blk * 256 + threadIdx.x) * 4;
    if (e0 < N_EDGES) {
        int4 d4 = *(const int4*)(eidx + N_EDGES + e0);
        if ((unsigned)d4.x < (unsigned)N_NODES) atomicAdd(&g_cnt[d4.x], 1);
        if ((unsigned)d4.y < (unsigned)N_NODES) atomicAdd(&g_cnt[d4.y], 1);
        if ((unsigned)d4.z < (unsigned)N_NODES) atomicAdd(&g_cnt[d4.z], 1);
        if ((unsigned)d4.w < (unsigned)N_NODES) atomicAdd(&g_cnt[d4.w], 1);
    }
}

// ---------------- fill device body -------------------------------------------
__device__ __forceinline__ void fill_body(const int* __restrict__ eidx, int blk) {
    int e0 = (blk * 256 + threadIdx.x) * 4;
    if (e0 < N_EDGES) {
        int4 s4 = *(const int4*)(eidx + e0);
        int4 d4 = *(const int4*)(eidx + N_EDGES + e0);
#pragma unroll
        for (int j = 0; j < 4; j++) {
            int s = (j == 0) ? s4.x : (j == 1) ? s4.y : (j == 2) ? s4.z : s4.w;
            int d = (j == 0) ? d4.x : (j == 1) ? d4.y : (j == 2) ? d4.z : d4.w;
            if ((unsigned)s < (unsigned)N_NODES && (unsigned)d < (unsigned)N_NODES) {
                int p = atomicAdd(&g_cur[d], 1);
                g_src[p] = s;
            }
        }
    }
}

// ---------------- bucket offsets: block scan + atomic block base -------------
__global__ void offsets_kernel() {
    __shared__ int sh[1024];
    __shared__ int sbase;
    int tid = threadIdx.x;
    int gid = blockIdx.x * 1024 + tid;
    int v = 0;
    if (gid < N_NODES) {
        int c = g_cnt[gid];
        g_cnt[gid] = 0;                  // restore for next replay
        g_len[gid] = c;
        v = c;
        g_dinv[gid] = rsqrtf((float)(c + 1));   // +1 self-loop
    }
    sh[tid] = v;
    __syncthreads();
    for (int o = 1; o < 1024; o <<= 1) {
        int x = (tid >= o) ? sh[tid - o] : 0;
        __syncthreads();
        sh[tid] += x;
        __syncthreads();
    }
    if (tid == 1023) sbase = atomicAdd(&g_total, sh[1023]);
    __syncthreads();
    if (gid < N_NODES) {
        int start = sbase + sh[tid] - v;
        g_off[gid] = start;
        g_cur[gid] = start;
    }
}

// ---------------- GEMM device body -------------------------------------------
// SCALE_EPI: multiply rows by g_dinv[m] in the epilogue (only valid once
// offsets_kernel has produced g_dinv — true for gemm2, NOT for gemm1 slices).
template<int K, bool SCALE_EPI>
__device__ __forceinline__ void gemm_body(const float* __restrict__ A,
                                          const float* __restrict__ W,
                                          float* __restrict__ C,
                                          int blk) {
    __shared__ float sA[16][260];
    __shared__ float sW[16][68];

    const int tid = threadIdx.x;
    const int m0  = blk * 256;
    const int tr  = tid >> 3;
    const int tc  = tid & 7;
    const int lr  = tid >> 2;
    const int lq  = tid & 3;
    const int wk  = tid >> 4;
    const int wc  = (tid & 15) << 2;

    float acc[8][8];
#pragma unroll
    for (int i = 0; i < 8; i++)
#pragma unroll
        for (int j = 0; j < 8; j++) acc[i][j] = 0.f;

    float4 pa[4];
    float4 pw;

#pragma unroll
    for (int p = 0; p < 4; p++) {
        int m = m0 + p * 64 + lr;
        int msafe = (m < N_NODES) ? m : (N_NODES - 1);
        pa[p] = *(const float4*)(A + (size_t)msafe * K + lq * 4);
    }
    pw = *(const float4*)(W + (size_t)wk * 64 + wc);

    for (int k0 = 0; k0 < K; k0 += 16) {
#pragma unroll
        for (int p = 0; p < 4; p++) {
            int mm = p * 64 + lr;
            sA[lq * 4 + 0][mm] = pa[p].x;
            sA[lq * 4 + 1][mm] = pa[p].y;
            sA[lq * 4 + 2][mm] = pa[p].z;
            sA[lq * 4 + 3][mm] = pa[p].w;
        }
        *(float4*)&sW[wk][wc] = pw;
        __syncthreads();

        if (k0 + 16 < K) {
#pragma unroll
            for (int p = 0; p < 4; p++) {
                int m = m0 + p * 64 + lr;
                int msafe = (m < N_NODES) ? m : (N_NODES - 1);
                pa[p] = *(const float4*)(A + (size_t)msafe * K + k0 + 16 + lq * 4);
            }
            pw = *(const float4*)(W + (size_t)(k0 + 16 + wk) * 64 + wc);
        }

#pragma unroll
        for (int k = 0; k < 16; k++) {
            float4 a0 = *(const float4*)&sA[k][tr * 8];
            float4 a1 = *(const float4*)&sA[k][tr * 8 + 4];
            float4 w0 = *(const float4*)&sW[k][tc * 4];
            float4 w1 = *(const float4*)&sW[k][tc * 4 + 32];
            float a[8] = {a0.x, a0.y, a0.z, a0.w, a1.x, a1.y, a1.z, a1.w};
            float w[8] = {w0.x, w0.y, w0.z, w0.w, w1.x, w1.y, w1.z, w1.w};
#pragma unroll
            for (int i = 0; i < 8; i++)
#pragma unroll
                for (int j = 0; j < 8; j++)
                    acc[i][j] += a[i] * w[j];
        }
        __syncthreads();
    }

#pragma unroll
    for (int i = 0; i < 8; i++) {
        int m = m0 + tr * 8 + i;
        if (m < N_NODES) {
            float s = SCALE_EPI ? g_dinv[m] : 1.0f;
            float4 o0 = make_float4(s * acc[i][0], s * acc[i][1], s * acc[i][2], s * acc[i][3]);
            float4 o1 = make_float4(s * acc[i][4], s * acc[i][5], s * acc[i][6], s * acc[i][7]);
            *(float4*)(C + (size_t)m * 64 + tc * 4)      = o0;
            *(float4*)(C + (size_t)m * 64 + tc * 4 + 32) = o1;
        }
    }
}

// ---------------- combined launches ------------------------------------------
// stage 1: gemm1 slice A (unscaled) alongside hist
__global__ __launch_bounds__(256, 2)
void hist_gemm1a_kernel(const int* __restrict__ eidx,
                        const float* __restrict__ x,
                        const float* __restrict__ W1) {
    if (blockIdx.x < G1A) {
        gemm_body<IN_DIM, false>(x, W1, g_h, blockIdx.x);
    } else {
        hist_body(eidx, blockIdx.x - G1A);
    }
}

// stage 3: gemm1 slice B (unscaled) alongside fill
__global__ __launch_bounds__(256, 2)
void fill_gemm1b_kernel(const int* __restrict__ eidx,
                        const float* __restrict__ x,
                        const float* __restrict__ W1) {
    if (blockIdx.x < G1B) {
        gemm_body<IN_DIM, false>(x, W1, g_h, G1A + blockIdx.x);
    } else {
        fill_body(eidx, blockIdx.x - G1B);
    }
}

// stage 4: apply dinv row scale to the whole h matrix (~3us, DRAM-streaming)
__global__ __launch_bounds__(256)
void scale_kernel() {
    int idx = blockIdx.x * 1024 + threadIdx.x * 4;
    if (idx < N_NODES * 64) {
        int m = idx >> 6;
        float s = g_dinv[m];
        float4 v = *(float4*)(g_h + idx);
        v.x *= s; v.y *= s; v.z *= s; v.w *= s;
        *(float4*)(g_h + idx) = v;
    }
}

__global__ __launch_bounds__(256, 2)
void gemm2_kernel(const float* __restrict__ W2) {
    gemm_body<HID_DIM, true>((const float*)g_a, W2, g_h, blockIdx.x);
}

// ---------------- CSR aggregation ------------------------------------------
// out[v] = (opt relu)( dinv[v] * (h~[v] + sum_e h~[src_e]) + b )
// Warp split into two half-warps (even/odd edges), float4 per lane.
template<bool RELU, bool OUT_SCRATCH>
__global__ __launch_bounds__(256)
void agg_kernel(const float* __restrict__ bias, float* __restrict__ outext) {
    const float* __restrict__ h = (const float*)g_h;
    float* __restrict__ out = OUT_SCRATCH ? (float*)g_a : outext;

    int warp = (blockIdx.x * blockDim.x + threadIdx.x) >> 5;
    int lane = threadIdx.x & 31;
    if (warp >= N_NODES) return;
    const int v = warp;
    const int half = lane >> 4;          // 0: even edges + self, 1: odd edges
    const int fl   = (lane & 15) << 2;   // feature offset

    float4 acc;
    if (half == 0) {
        acc = *(const float4*)(h + (size_t)v * 64 + fl);   // self term
    } else {
        acc = make_float4(0.f, 0.f, 0.f, 0.f);
    }

    int beg = g_off[v];
    int end = beg + g_len[v];
#pragma unroll 4
    for (int i = beg + half; i < end; i += 2) {
        int s = g_src[i];
        float4 m = *(const float4*)(h + (size_t)s * 64 + fl);
        acc.x += m.x;
        acc.y += m.y;
        acc.z += m.z;
        acc.w += m.w;
    }

    acc.x += __shfl_xor_sync(0xFFFFFFFFu, acc.x, 16);
    acc.y += __shfl_xor_sync(0xFFFFFFFFu, acc.y, 16);
    acc.z += __shfl_xor_sync(0xFFFFFFFFu, acc.z, 16);
    acc.w += __shfl_xor_sync(0xFFFFFFFFu, acc.w, 16);

    if (half == 0) {
        float di = g_dinv[v];
        float4 b = *(const float4*)(bias + fl);
        acc.x = di * acc.x + b.x;
        acc.y = di * acc.y + b.y;
        acc.z = di * acc.z + b.z;
        acc.w = di * acc.w + b.w;
        if (RELU) {
            acc.x = fmaxf(acc.x, 0.f);
            acc.y = fmaxf(acc.y, 0.f);
            acc.z = fmaxf(acc.z, 0.f);
            acc.w = fmaxf(acc.w, 0.f);
        }
        *(float4*)(out + (size_t)v * 64 + fl) = acc;
    }
}

// ---------------- launch (single stream, capture-safe) -----------------------
extern "C" void kernel_launch(void* const* d_in, const int* in_sizes, int n_in,
                              void* d_out, int out_size) {
    const float* x    = (const float*)d_in[0];
    const int*   eidx = (const int*)d_in[1];     // int32 [2, N_EDGES]
    const float* W1   = (const float*)d_in[2];
    const float* b1   = (const float*)d_in[3];
    const float* W2   = (const float*)d_in[4];
    const float* b2   = (const float*)d_in[5];
    float*       out  = (float*)d_out;

    const int scan_blocks = (N_NODES + 1023) / 1024;        // 98
    const int agg_blocks  = (N_NODES + 7) / 8;

    // stage 1: hist + gemm1 slice A (overlapped)
    hist_gemm1a_kernel<<<G1A + EDGE4_BLOCKS, 256>>>(eidx, x, W1);
    // stage 2: offsets (g_dinv/g_off/g_cur/g_len ready after this)
    offsets_kernel<<<scan_blocks, 1024>>>();
    // stage 3: fill + gemm1 slice B (overlapped)
    fill_gemm1b_kernel<<<G1B + EDGE4_BLOCKS, 256>>>(eidx, x, W1);
    // stage 4: dinv row-scale of h
    scale_kernel<<<SCALE_BLOCKS, 256>>>();

    // layer 1 aggregation
    agg_kernel<true, true><<<agg_blocks, 256>>>(b1, nullptr);

    // layer 2
    gemm2_kernel<<<GEMM_BLOCKS, 256>>>(W2);
    agg_kernel<false, false><<<agg_blocks, 256>>>(b2, out);
}

// round 17
// speedup vs baseline: 1.1152x; 1.1152x over previous
#include <cuda_runtime.h>
#include <cuda_fp16.h>
#include <stdint.h>

#define N_NODES 100000
#define N_EDGES 1600000
#define IN_DIM  128
#define HID_DIM 64
#define OUT_DIM 64

#define GEMM_BLOCKS ((N_NODES + 255) / 256)        // 391
#define EDGE4_BLOCKS ((N_EDGES / 4 + 255) / 256)   // 1563
#define AGG_BLOCKS  ((N_NODES + 7) / 8)            // 12500

// ---------------- scratch (static device globals; no allocation) -------------
// Zero-initialized at load; offsets re-zeroes g_cnt and hist resets g_total,
// so every graph replay sees identical state.
__device__ __align__(16) __half g_hh[N_NODES * 64]; // GEMM output, dinv-scaled, fp16
__device__ __align__(16) float  g_a[N_NODES * 64];  // layer1 activations (fp32)
__device__ __align__(16) int    g_cnt[N_NODES];     // hist counters
__device__ __align__(16) int    g_len[N_NODES];     // in-degree snapshot
__device__ __align__(16) int    g_cur[N_NODES];     // fill cursor
__device__ __align__(16) float  g_dinv[N_NODES];    // rsqrt(deg+1)
__device__ __align__(16) int    g_off[N_NODES];     // bucket start
__device__ __align__(16) int    g_src[N_EDGES];     // source id only
__device__ int g_total;                             // global bucket cursor

// ---------------- hist ------------------------------------------------------
__global__ void hist_kernel(const int* __restrict__ eidx) {
    if (blockIdx.x == 0 && threadIdx.x == 0) g_total = 0;
    int e0 = (blockIdx.x * blockDim.x + threadIdx.x) * 4;
    if (e0 < N_EDGES) {
        int4 d4 = *(const int4*)(eidx + N_EDGES + e0);
        if ((unsigned)d4.x < (unsigned)N_NODES) atomicAdd(&g_cnt[d4.x], 1);
        if ((unsigned)d4.y < (unsigned)N_NODES) atomicAdd(&g_cnt[d4.y], 1);
        if ((unsigned)d4.z < (unsigned)N_NODES) atomicAdd(&g_cnt[d4.z], 1);
        if ((unsigned)d4.w < (unsigned)N_NODES) atomicAdd(&g_cnt[d4.w], 1);
    }
}

// ---------------- offsets: block scan + atomic base; resets g_cnt ------------
__global__ void offsets_kernel() {
    __shared__ int sh[1024];
    __shared__ int sbase;
    int tid = threadIdx.x;
    int gid = blockIdx.x * 1024 + tid;
    int v = 0;
    if (gid < N_NODES) {
        int c = g_cnt[gid];
        g_cnt[gid] = 0;                  // restore for next replay
        g_len[gid] = c;
        v = c;
        g_dinv[gid] = rsqrtf((float)(c + 1));   // +1 self-loop
    }
    sh[tid] = v;
    __syncthreads();
    for (int o = 1; o < 1024; o <<= 1) {
        int x = (tid >= o) ? sh[tid - o] : 0;
        __syncthreads();
        sh[tid] += x;
        __syncthreads();
    }
    if (tid == 1023) sbase = atomicAdd(&g_total, sh[1023]);
    __syncthreads();
    if (gid < N_NODES) {
        int start = sbase + sh[tid] - v;
        g_off[gid] = start;
        g_cur[gid] = start;
    }
}

// ---------------- fill device body ------------------------------------------
__device__ __forceinline__ void fill_body(const int* __restrict__ eidx, int blk) {
    int e0 = (blk * 256 + threadIdx.x) * 4;
    if (e0 < N_EDGES) {
        int4 s4 = *(const int4*)(eidx + e0);
        int4 d4 = *(const int4*)(eidx + N_EDGES + e0);
#pragma unroll
        for (int j = 0; j < 4; j++) {
            int s = (j == 0) ? s4.x : (j == 1) ? s4.y : (j == 2) ? s4.z : s4.w;
            int d = (j == 0) ? d4.x : (j == 1) ? d4.y : (j == 2) ? d4.z : d4.w;
            if ((unsigned)s < (unsigned)N_NODES && (unsigned)d < (unsigned)N_NODES) {
                int p = atomicAdd(&g_cur[d], 1);
                g_src[p] = s;
            }
        }
    }
}

// ---------------- GEMM body: g_hh[m] = fp16( dinv[m] * (A[m][:] @ W) ) -------
// Tile 256 rows x 64 cols, K staged 16 at a time, register-staged prefetch.
// Epilogue: dinv row-scale + fp16 conversion (g_dinv ready: offsets ran first).
template<int K>
__device__ __forceinline__ void gemm_body(const float* __restrict__ A,
                                          const float* __restrict__ W,
                                          int blk) {
    __shared__ float sA[16][260];
    __shared__ float sW[16][68];

    const int tid = threadIdx.x;
    const int m0  = blk * 256;
    const int tr  = tid >> 3;
    const int tc  = tid & 7;
    const int lr  = tid >> 2;
    const int lq  = tid & 3;
    const int wk  = tid >> 4;
    const int wc  = (tid & 15) << 2;

    float acc[8][8];
#pragma unroll
    for (int i = 0; i < 8; i++)
#pragma unroll
        for (int j = 0; j < 8; j++) acc[i][j] = 0.f;

    float4 pa[4];
    float4 pw;
#pragma unroll
    for (int p = 0; p < 4; p++) {
        int m = m0 + p * 64 + lr;
        int msafe = (m < N_NODES) ? m : (N_NODES - 1);
        pa[p] = *(const float4*)(A + (size_t)msafe * K + lq * 4);
    }
    pw = *(const float4*)(W + (size_t)wk * 64 + wc);

    for (int k0 = 0; k0 < K; k0 += 16) {
#pragma unroll
        for (int p = 0; p < 4; p++) {
            int mm = p * 64 + lr;
            sA[lq * 4 + 0][mm] = pa[p].x;
            sA[lq * 4 + 1][mm] = pa[p].y;
            sA[lq * 4 + 2][mm] = pa[p].z;
            sA[lq * 4 + 3][mm] = pa[p].w;
        }
        *(float4*)&sW[wk][wc] = pw;
        __syncthreads();

        if (k0 + 16 < K) {
#pragma unroll
            for (int p = 0; p < 4; p++) {
                int m = m0 + p * 64 + lr;
                int msafe = (m < N_NODES) ? m : (N_NODES - 1);
                pa[p] = *(const float4*)(A + (size_t)msafe * K + k0 + 16 + lq * 4);
            }
            pw = *(const float4*)(W + (size_t)(k0 + 16 + wk) * 64 + wc);
        }

#pragma unroll
        for (int k = 0; k < 16; k++) {
            float4 a0 = *(const float4*)&sA[k][tr * 8];
            float4 a1 = *(const float4*)&sA[k][tr * 8 + 4];
            float4 w0 = *(const float4*)&sW[k][tc * 4];
            float4 w1 = *(const float4*)&sW[k][tc * 4 + 32];
            float a[8] = {a0.x, a0.y, a0.z, a0.w, a1.x, a1.y, a1.z, a1.w};
            float w[8] = {w0.x, w0.y, w0.z, w0.w, w1.x, w1.y, w1.z, w1.w};
#pragma unroll
            for (int i = 0; i < 8; i++)
#pragma unroll
                for (int j = 0; j < 8; j++)
                    acc[i][j] += a[i] * w[j];
        }
        __syncthreads();
    }

#pragma unroll
    for (int i = 0; i < 8; i++) {
        int m = m0 + tr * 8 + i;
        if (m < N_NODES) {
            float s = g_dinv[m];
            // cols tc*4..tc*4+3 (8B) and tc*4+32..+35 (8B), fp16
            __half2 h0 = __float22half2_rn(make_float2(s * acc[i][0], s * acc[i][1]));
            __half2 h1 = __float22half2_rn(make_float2(s * acc[i][2], s * acc[i][3]));
            __half2 h2 = __float22half2_rn(make_float2(s * acc[i][4], s * acc[i][5]));
            __half2 h3 = __float22half2_rn(make_float2(s * acc[i][6], s * acc[i][7]));
            *(__half2*)(g_hh + (size_t)m * 64 + tc * 4)      = h0;
            *(__half2*)(g_hh + (size_t)m * 64 + tc * 4 + 2)  = h1;
            *(__half2*)(g_hh + (size_t)m * 64 + tc * 4 + 32) = h2;
            *(__half2*)(g_hh + (size_t)m * 64 + tc * 4 + 34) = h3;
        }
    }
}

// ---------------- combined fill + gemm1 --------------------------------------
__global__ __launch_bounds__(256, 2)
void fill_gemm1_kernel(const int* __restrict__ eidx,
                       const float* __restrict__ x,
                       const float* __restrict__ W1) {
    if (blockIdx.x < GEMM_BLOCKS) {
        gemm_body<IN_DIM>(x, W1, blockIdx.x);
    } else {
        fill_body(eidx, blockIdx.x - GEMM_BLOCKS);
    }
}

__global__ __launch_bounds__(256, 2)
void gemm2_kernel(const float* __restrict__ W2) {
    gemm_body<HID_DIM>((const float*)g_a, W2, blockIdx.x);
}

// ---------------- CSR aggregation (fp16 gather, fp32 accumulate) -------------
// out[v] = (opt relu)( dinv[v] * (h~[v] + sum_e h~[src_e]) + b )
// Warp per node, two half-warps (even/odd edges); lane = 4 features as
// uint2 (4 halves, 8B). Row = 128B -> half the L2 sector traffic of fp32.
template<bool RELU, bool OUT_SCRATCH>
__global__ __launch_bounds__(256)
void agg_kernel(const float* __restrict__ bias, float* __restrict__ outext) {
    const __half* __restrict__ h = (const __half*)g_hh;
    float* __restrict__ out = OUT_SCRATCH ? (float*)g_a : outext;

    int warp = (blockIdx.x * blockDim.x + threadIdx.x) >> 5;
    int lane = threadIdx.x & 31;
    if (warp >= N_NODES) return;
    const int v = warp;
    const int half_id = lane >> 4;       // 0: even edges + self, 1: odd edges
    const int fl      = (lane & 15) << 2;// feature offset (0,4,...,60)

    float4 acc = make_float4(0.f, 0.f, 0.f, 0.f);
    if (half_id == 0) {
        uint2 raw = *(const uint2*)(h + (size_t)v * 64 + fl);   // self term
        float2 f0 = __half22float2(*reinterpret_cast<__half2*>(&raw.x));
        float2 f1 = __half22float2(*reinterpret_cast<__half2*>(&raw.y));
        acc = make_float4(f0.x, f0.y, f1.x, f1.y);
    }

    int beg = g_off[v];
    int end = beg + g_len[v];
#pragma unroll 4
    for (int i = beg + half_id; i < end; i += 2) {
        int s = g_src[i];
        uint2 raw = *(const uint2*)(h + (size_t)s * 64 + fl);
        float2 f0 = __half22float2(*reinterpret_cast<__half2*>(&raw.x));
        float2 f1 = __half22float2(*reinterpret_cast<__half2*>(&raw.y));
        acc.x += f0.x;
        acc.y += f0.y;
        acc.z += f1.x;
        acc.w += f1.y;
    }

    acc.x += __shfl_xor_sync(0xFFFFFFFFu, acc.x, 16);
    acc.y += __shfl_xor_sync(0xFFFFFFFFu, acc.y, 16);
    acc.z += __shfl_xor_sync(0xFFFFFFFFu, acc.z, 16);
    acc.w += __shfl_xor_sync(0xFFFFFFFFu, acc.w, 16);

    if (half_id == 0) {
        float di = g_dinv[v];
        float4 b = *(const float4*)(bias + fl);
        acc.x = di * acc.x + b.x;
        acc.y = di * acc.y + b.y;
        acc.z = di * acc.z + b.z;
        acc.w = di * acc.w + b.w;
        if (RELU) {
            acc.x = fmaxf(acc.x, 0.f);
            acc.y = fmaxf(acc.y, 0.f);
            acc.z = fmaxf(acc.z, 0.f);
            acc.w = fmaxf(acc.w, 0.f);
        }
        *(float4*)(out + (size_t)v * 64 + fl) = acc;
    }
}

// ---------------- launch (single stream, capture-safe; R12 structure) --------
extern "C" void kernel_launch(void* const* d_in, const int* in_sizes, int n_in,
                              void* d_out, int out_size) {
    const float* x    = (const float*)d_in[0];
    const int*   eidx = (const int*)d_in[1];     // int32 [2, N_EDGES]
    const float* W1   = (const float*)d_in[2];
    const float* b1   = (const float*)d_in[3];
    const float* W2   = (const float*)d_in[4];
    const float* b2   = (const float*)d_in[5];
    float*       out  = (float*)d_out;

    const int scan_blocks = (N_NODES + 1023) / 1024;        // 98

    // build prefix
    hist_kernel<<<EDGE4_BLOCKS, 256>>>(eidx);
    offsets_kernel<<<scan_blocks, 1024>>>();

    // fill + gemm1 overlapped (g_dinv ready for gemm1 epilogue)
    fill_gemm1_kernel<<<GEMM_BLOCKS + EDGE4_BLOCKS, 256>>>(eidx, x, W1);

    // layer 1 aggregation: g_a = relu(dinv*(sum)+b1)   (fp32 out)
    agg_kernel<true, true><<<AGG_BLOCKS, 256>>>(b1, nullptr);

    // layer 2
    gemm2_kernel<<<GEMM_BLOCKS, 256>>>(W2);
    agg_kernel<false, false><<<AGG_BLOCKS, 256>>>(b2, out);
}